// round 3
// baseline (speedup 1.0000x reference)
#include <cuda_runtime.h>
#include <cstdint>

#define TT 1024
#define BB 512
#define HH 15
#define II 10
#define OO 128

// Scratch for hidden states: [T][B][16] (H=15 padded to 16 for aligned vector IO)
__device__ float g_hs[(size_t)TT * BB * 16];

typedef unsigned long long ull;

__device__ __forceinline__ ull pk(float lo, float hi) {
    ull r; asm("mov.b64 %0, {%1, %2};" : "=l"(r) : "f"(lo), "f"(hi)); return r;
}
__device__ __forceinline__ void upk(ull v, float& lo, float& hi) {
    asm("mov.b64 {%0, %1}, %2;" : "=f"(lo), "=f"(hi) : "l"(v));
}
__device__ __forceinline__ ull fma2(ull a, ull b, ull c) {
    ull d; asm("fma.rn.f32x2 %0, %1, %2, %3;" : "=l"(d) : "l"(a), "l"(b), "l"(c)); return d;
}
__device__ __forceinline__ ull add2(ull a, ull b) {
    ull d; asm("add.rn.f32x2 %0, %1, %2;" : "=l"(d) : "l"(a), "l"(b)); return d;
}

// Pre-scaled sigmoid: input g already multiplied by -log2(e).
// sigmoid = 1 / (1 + 2^g)
__device__ __forceinline__ float fsig_pre(float g) {
    float e; asm("ex2.approx.f32 %0, %1;" : "=f"(e) : "f"(g));
    float d = e + 1.0f;
    float r; asm("rcp.approx.f32 %0, %1;" : "=f"(r) : "f"(d));
    return r;
}
// Pre-scaled tanh: input g already multiplied by 2*log2(e).
// tanh = 1 - 2/(1 + 2^g)
__device__ __forceinline__ float ftanh_pre(float g) {
    float e; asm("ex2.approx.f32 %0, %1;" : "=f"(e) : "f"(g));
    float d = e + 1.0f;
    float r; asm("rcp.approx.f32 %0, %1;" : "=f"(r) : "f"(d));
    return 1.0f - 2.0f * r;
}
// Plain accurate sigmoid (phase 2)
__device__ __forceinline__ float fsig(float x) {
    float e; asm("ex2.approx.f32 %0, %1;" : "=f"(e) : "f"(-1.4426950408889634f * x));
    float d = e + 1.0f;
    float r; asm("rcp.approx.f32 %0, %1;" : "=f"(r) : "f"(d));
    return r;
}

#define NEG_LOG2E (-1.4426950408889634f)
#define TWO_LOG2E ( 2.8853900817779268f)

// Rebroadcast scalar h (lane j holds h[j], j<15) into 8 packed pairs on every lane.
#define BCAST(hv, hp)                                                          \
    do {                                                                       \
        _Pragma("unroll")                                                      \
        for (int _i = 0; _i < 7; _i++) {                                       \
            float _lo = __shfl_sync(0xffffffffu, (hv), 2 * _i);                \
            float _hi = __shfl_sync(0xffffffffu, (hv), 2 * _i + 1);            \
            (hp)[_i] = pk(_lo, _hi);                                           \
        }                                                                      \
        {                                                                      \
            float _lo = __shfl_sync(0xffffffffu, (hv), 14);                    \
            (hp)[7] = pk(_lo, 0.0f);                                           \
        }                                                                      \
    } while (0)

// ---------------------------------------------------------------------------
// Phase 1: recurrence. One warp per batch element. Lanes 0..14 own hidden
// units; h state replicated across lanes as 8 f32x2 pairs via shuffles.
// r/z gate weights pre-scaled by -log2(e); n gate by 2*log2(e) so the
// activation FMULs vanish from the critical path.
// ---------------------------------------------------------------------------
__global__ void __launch_bounds__(128, 1) gru_rec(
    const float* __restrict__ feed, const float* __restrict__ h0,
    const float* __restrict__ W_ih, const float* __restrict__ W_hh,
    const float* __restrict__ b_ih, const float* __restrict__ b_hh)
{
    const int lane = threadIdx.x & 31;
    const int b    = blockIdx.x * 4 + (threadIdx.x >> 5);   // 128 blocks x 4 warps = 512
    const int j    = (lane < HH) ? lane : 0;                // inactive lanes shadow unit 0

    // W_hh rows j (r), 15+j (z), 30+j (n) packed over k (k=15 padded with 0),
    // pre-scaled per gate.
    ull wr[8], wz[8], wn[8];
#pragma unroll
    for (int i = 0; i < 8; i++) {
        const int k0 = 2 * i, k1 = 2 * i + 1;
        float r0 = W_hh[j * HH + k0]            * NEG_LOG2E;
        float z0 = W_hh[(HH + j) * HH + k0]     * NEG_LOG2E;
        float n0 = W_hh[(2 * HH + j) * HH + k0] * TWO_LOG2E;
        float r1 = (k1 < HH) ? W_hh[j * HH + k1]            * NEG_LOG2E : 0.0f;
        float z1 = (k1 < HH) ? W_hh[(HH + j) * HH + k1]     * NEG_LOG2E : 0.0f;
        float n1 = (k1 < HH) ? W_hh[(2 * HH + j) * HH + k1] * TWO_LOG2E : 0.0f;
        wr[i] = pk(r0, r1); wz[i] = pk(z0, z1); wn[i] = pk(n0, n1);
    }

    // Input projection folded into gate constants:
    //   cr = (i_r + b_hh_r) * -log2e ; cz likewise ; cn = i_n * 2log2e ;
    //   bn = b_hh_n * 2log2e
    float cr = b_ih[j]          + b_hh[j];
    float cz = b_ih[HH + j]     + b_hh[HH + j];
    float cn = b_ih[2 * HH + j];
    float bn = b_hh[2 * HH + j] * TWO_LOG2E;
#pragma unroll
    for (int k = 0; k < II; k++) {
        float xk = feed[b * II + k];
        cr = fmaf(xk, W_ih[j * II + k],            cr);
        cz = fmaf(xk, W_ih[(HH + j) * II + k],     cz);
        cn = fmaf(xk, W_ih[(2 * HH + j) * II + k], cn);
    }
    cr *= NEG_LOG2E;
    cz *= NEG_LOG2E;
    cn *= TWO_LOG2E;

    float h = (lane < HH) ? h0[b * HH + j] : 0.0f;

    ull hp[8];
    BCAST(h, hp);

    const ull crp = pk(cr, 0.0f);
    const ull czp = pk(cz, 0.0f);
    const ull bnp = pk(bn, 0.0f);

    // per-t store pointer for this lane (lanes 0..7 store 8B each = 64B row)
    float* sp = g_hs + (size_t)b * 16 + lane * 2;
    const bool do_store = (lane < 8);

    for (int t = 0; t < TT; t++) {
        // 3 gate dots, 2 interleaved accumulator chains each (depth 4)
        ull ar0 = crp, az0 = czp, an0 = bnp;
        ull ar1 = 0ULL, az1 = 0ULL, an1 = 0ULL;
#pragma unroll
        for (int i = 0; i < 4; i++) {
            ar0 = fma2(wr[i], hp[i], ar0);
            az0 = fma2(wz[i], hp[i], az0);
            an0 = fma2(wn[i], hp[i], an0);
        }
#pragma unroll
        for (int i = 4; i < 8; i++) {
            ar1 = fma2(wr[i], hp[i], ar1);
            az1 = fma2(wz[i], hp[i], az1);
            an1 = fma2(wn[i], hp[i], an1);
        }
        float rl, rh, zl, zh, nl, nh;
        upk(add2(ar0, ar1), rl, rh);
        upk(add2(az0, az1), zl, zh);
        upk(add2(an0, an1), nl, nh);
        const float gr = rl + rh;     // pre-scaled by -log2e
        const float gz = zl + zh;     // pre-scaled by -log2e
        const float gn = nl + nh;     // pre-scaled by 2log2e

        const float r   = fsig_pre(gr);
        const float z   = fsig_pre(gz);
        const float omz = 1.0f - z;       // early, off n-path
        const float zh2 = z * h;          // early, off n-path
        const float n   = ftanh_pre(fmaf(r, gn, cn));
        h = fmaf(omz, n, zh2);            // (1-z)*n + z*h, +4cyc after tanh

        BCAST(h, hp);

        if (do_store) *reinterpret_cast<ull*>(sp) = hp[lane];
        sp += BB * 16;
    }
}

// ---------------------------------------------------------------------------
// Phase 2: out[t,b,o] = sigmoid(hs[t,b,:] . W_out[o,:] + b_out[o])
// One warp per (t,b) row iteration; lane handles 4 fixed output columns with
// W_out held in registers as f32x2 pairs. HBM-store bound by design.
// ---------------------------------------------------------------------------
__global__ void __launch_bounds__(256, 2) gru_out(
    const float* __restrict__ W_out, const float* __restrict__ b_out,
    float* __restrict__ out)
{
    __shared__ float sw[OO * 16];
    __shared__ float sb[OO];
    for (int i = threadIdx.x; i < OO * 16; i += blockDim.x) {
        int o = i >> 4, k = i & 15;
        sw[i] = (k < HH) ? W_out[o * HH + k] : 0.0f;
    }
    for (int i = threadIdx.x; i < OO; i += blockDim.x) sb[i] = b_out[i];
    __syncthreads();

    const int lane = threadIdx.x & 31;
    const int o0   = lane * 4;

    ull wv[4][8];
    ull bo2[4];
#pragma unroll
    for (int oo = 0; oo < 4; oo++) {
        bo2[oo] = pk(sb[o0 + oo], 0.0f);
#pragma unroll
        for (int i = 0; i < 8; i++)
            wv[oo][i] = *reinterpret_cast<const ull*>(&sw[(o0 + oo) * 16 + 2 * i]);
    }

    const int warp_global = blockIdx.x * (blockDim.x >> 5) + (threadIdx.x >> 5);
    const int nwarps      = gridDim.x * (blockDim.x >> 5);
    const int P           = TT * BB;

    for (int p = warp_global; p < P; p += nwarps) {
        const ulonglong2* hr = reinterpret_cast<const ulonglong2*>(g_hs + (size_t)p * 16);
        ulonglong2 q0 = hr[0], q1 = hr[1], q2 = hr[2], q3 = hr[3];
        ull hp[8] = {q0.x, q0.y, q1.x, q1.y, q2.x, q2.y, q3.x, q3.y};

        float res[4];
#pragma unroll
        for (int oo = 0; oo < 4; oo++) {
            ull a0 = bo2[oo], a1 = 0ULL;
#pragma unroll
            for (int i = 0; i < 4; i++) {
                a0 = fma2(wv[oo][2 * i],     hp[2 * i],     a0);
                a1 = fma2(wv[oo][2 * i + 1], hp[2 * i + 1], a1);
            }
            float lo, hi;
            upk(add2(a0, a1), lo, hi);
            res[oo] = fsig(lo + hi);
        }
        float4 v = make_float4(res[0], res[1], res[2], res[3]);
        *reinterpret_cast<float4*>(out + (size_t)p * OO + o0) = v;
    }
}

extern "C" void kernel_launch(void* const* d_in, const int* in_sizes, int n_in,
                              void* d_out, int out_size)
{
    (void)in_sizes; (void)n_in; (void)out_size;
    const float* feed  = (const float*)d_in[0];
    const float* h0    = (const float*)d_in[1];
    const float* W_ih  = (const float*)d_in[2];
    const float* W_hh  = (const float*)d_in[3];
    const float* b_ih  = (const float*)d_in[4];
    const float* b_hh  = (const float*)d_in[5];
    const float* W_out = (const float*)d_in[6];
    const float* b_out = (const float*)d_in[7];
    float* out = (float*)d_out;

    gru_rec<<<128, 128>>>(feed, h0, W_ih, W_hh, b_ih, b_hh);
    gru_out<<<1184, 256>>>(W_out, b_out, out);
}

// round 5
// speedup vs baseline: 1.3315x; 1.3315x over previous
#include <cuda_runtime.h>
#include <cstdint>

#define TT 1024
#define BB 512
#define HH 15
#define II 10
#define OO 128
#define RING 32          // h-row ring depth per batch (must be power of 2)
#define GUARD 16         // producer checks consumer every GUARD steps

typedef unsigned long long ull;

__device__ __forceinline__ ull pk(float lo, float hi) {
    ull r; asm("mov.b64 %0, {%1, %2};" : "=l"(r) : "f"(lo), "f"(hi)); return r;
}
__device__ __forceinline__ void upk(ull v, float& lo, float& hi) {
    asm("mov.b64 {%0, %1}, %2;" : "=f"(lo), "=f"(hi) : "l"(v));
}
__device__ __forceinline__ ull fma2(ull a, ull b, ull c) {
    ull d; asm("fma.rn.f32x2 %0, %1, %2, %3;" : "=l"(d) : "l"(a), "l"(b), "l"(c)); return d;
}
__device__ __forceinline__ ull add2(ull a, ull b) {
    ull d; asm("add.rn.f32x2 %0, %1, %2;" : "=l"(d) : "l"(a), "l"(b)); return d;
}

// Pre-scaled sigmoid: input g already multiplied by -log2(e):  1/(1+2^g)
__device__ __forceinline__ float fsig_pre(float g) {
    float e; asm("ex2.approx.f32 %0, %1;" : "=f"(e) : "f"(g));
    float d = e + 1.0f;
    float r; asm("rcp.approx.f32 %0, %1;" : "=f"(r) : "f"(d));
    return r;
}
// Pre-scaled tanh: input g already multiplied by 2*log2(e): 1 - 2/(1+2^g)
__device__ __forceinline__ float ftanh_pre(float g) {
    float e; asm("ex2.approx.f32 %0, %1;" : "=f"(e) : "f"(g));
    float d = e + 1.0f;
    float r; asm("rcp.approx.f32 %0, %1;" : "=f"(r) : "f"(d));
    return 1.0f - 2.0f * r;
}
// Plain accurate sigmoid (projection)
__device__ __forceinline__ float fsig(float x) {
    float e; asm("ex2.approx.f32 %0, %1;" : "=f"(e) : "f"(-1.4426950408889634f * x));
    float d = e + 1.0f;
    float r; asm("rcp.approx.f32 %0, %1;" : "=f"(r) : "f"(d));
    return r;
}

#define NEG_LOG2E (-1.4426950408889634f)
#define TWO_LOG2E ( 2.8853900817779268f)

__device__ __forceinline__ uint32_t smem_u32(const void* p) {
    uint32_t a;
    asm("{ .reg .u64 t; cvta.to.shared.u64 t, %1; cvt.u32.u64 %0, t; }" : "=r"(a) : "l"(p));
    return a;
}
__device__ __forceinline__ void sts_v2u64(uint32_t addr, ull a, ull b) {
    asm volatile("st.shared.v2.u64 [%0], {%1, %2};" :: "r"(addr), "l"(a), "l"(b) : "memory");
}
__device__ __forceinline__ void lds_v2u64(uint32_t addr, ull& a, ull& b) {
    asm volatile("ld.shared.v2.u64 {%0, %1}, [%2];" : "=l"(a), "=l"(b) : "r"(addr) : "memory");
}
__device__ __forceinline__ void st_release_s32(uint32_t addr, int v) {
    asm volatile("st.release.cta.shared.u32 [%0], %1;" :: "r"(addr), "r"(v) : "memory");
}
__device__ __forceinline__ int ld_acquire_s32(uint32_t addr) {
    int v; asm volatile("ld.acquire.cta.shared.u32 %0, [%1];" : "=r"(v) : "r"(addr) : "memory");
    return v;
}

// Rebroadcast scalar h (lane j holds h[j], j<15) into 8 packed pairs on every lane.
#define BCAST(hv, hp)                                                          \
    do {                                                                       \
        _Pragma("unroll")                                                      \
        for (int _i = 0; _i < 7; _i++) {                                       \
            float _lo = __shfl_sync(0xffffffffu, (hv), 2 * _i);                \
            float _hi = __shfl_sync(0xffffffffu, (hv), 2 * _i + 1);            \
            (hp)[_i] = pk(_lo, _hi);                                           \
        }                                                                      \
        {                                                                      \
            float _lo = __shfl_sync(0xffffffffu, (hv), 14);                    \
            (hp)[7] = pk(_lo, 0.0f);                                           \
        }                                                                      \
    } while (0)

// ---------------------------------------------------------------------------
// Fused persistent kernel. Block = 8 warps:
//   warps 0..3 : GRU recurrence for batches blockIdx*4 + {0..3}
//   warps 4..7 : output projection consumers for the same batches
// Hidden rows flow through a 32-deep smem ring with release/acquire counters.
// ---------------------------------------------------------------------------
__global__ void __launch_bounds__(256, 1) gru_fused(
    const float* __restrict__ feed, const float* __restrict__ h0,
    const float* __restrict__ W_ih, const float* __restrict__ W_hh,
    const float* __restrict__ b_ih, const float* __restrict__ b_hh,
    const float* __restrict__ W_out, const float* __restrict__ b_out,
    float* __restrict__ out)
{
    __shared__ __align__(16) float hring[4][RING][16];   // 8 KB
    __shared__ int prod[4];
    __shared__ int cons[4];

    const int tid  = threadIdx.x;
    const int wid  = tid >> 5;
    const int lane = tid & 31;
    const int bl   = wid & 3;                       // batch slot within block
    const int b    = blockIdx.x * 4 + bl;           // global batch (128 blocks x 4)

    if (tid < 4) { prod[tid] = 0; cons[tid] = 0; }
    __syncthreads();

    const uint32_t ring_a = smem_u32(&hring[bl][0][0]);
    const uint32_t prod_a = smem_u32(&prod[bl]);
    const uint32_t cons_a = smem_u32(&cons[bl]);

    if (wid < 4) {
        // ================= producer: recurrence =================
        const int j = (lane < HH) ? lane : 0;       // inactive lanes shadow unit 0

        // W_hh rows j (r), 15+j (z), 30+j (n) packed over k, pre-scaled per gate
        ull wr[8], wz[8], wn[8];
#pragma unroll
        for (int i = 0; i < 8; i++) {
            const int k0 = 2 * i, k1 = 2 * i + 1;
            float r0 = W_hh[j * HH + k0]            * NEG_LOG2E;
            float z0 = W_hh[(HH + j) * HH + k0]     * NEG_LOG2E;
            float n0 = W_hh[(2 * HH + j) * HH + k0] * TWO_LOG2E;
            float r1 = (k1 < HH) ? W_hh[j * HH + k1]            * NEG_LOG2E : 0.0f;
            float z1 = (k1 < HH) ? W_hh[(HH + j) * HH + k1]     * NEG_LOG2E : 0.0f;
            float n1 = (k1 < HH) ? W_hh[(2 * HH + j) * HH + k1] * TWO_LOG2E : 0.0f;
            wr[i] = pk(r0, r1); wz[i] = pk(z0, z1); wn[i] = pk(n0, n1);
        }

        float cr = b_ih[j]          + b_hh[j];
        float cz = b_ih[HH + j]     + b_hh[HH + j];
        float cn = b_ih[2 * HH + j];
        float bn = b_hh[2 * HH + j] * TWO_LOG2E;
#pragma unroll
        for (int k = 0; k < II; k++) {
            float xk = feed[b * II + k];
            cr = fmaf(xk, W_ih[j * II + k],            cr);
            cz = fmaf(xk, W_ih[(HH + j) * II + k],     cz);
            cn = fmaf(xk, W_ih[(2 * HH + j) * II + k], cn);
        }
        cr *= NEG_LOG2E;
        cz *= NEG_LOG2E;
        cn *= TWO_LOG2E;

        float h = (lane < HH) ? h0[b * HH + j] : 0.0f;
        ull hp[8];
        BCAST(h, hp);

        const ull crp = pk(cr, 0.0f);
        const ull czp = pk(cz, 0.0f);
        const ull bnp = pk(bn, 0.0f);

        for (int t = 0; t < TT; t++) {
            // gate dots: 6 independent f32x2 chains
            ull ar0 = crp, az0 = czp, an0 = bnp;
            ull ar1 = 0ULL, az1 = 0ULL, an1 = 0ULL;
#pragma unroll
            for (int i = 0; i < 4; i++) {
                ar0 = fma2(wr[i], hp[i], ar0);
                az0 = fma2(wz[i], hp[i], az0);
                an0 = fma2(wn[i], hp[i], an0);
            }
#pragma unroll
            for (int i = 4; i < 8; i++) {
                ar1 = fma2(wr[i], hp[i], ar1);
                az1 = fma2(wz[i], hp[i], az1);
                an1 = fma2(wn[i], hp[i], an1);
            }
            float rl, rh, zl, zh, nl, nh;
            upk(add2(ar0, ar1), rl, rh);
            upk(add2(az0, az1), zl, zh);
            upk(add2(an0, an1), nl, nh);
            const float gr = rl + rh;     // * -log2e
            const float gz = zl + zh;     // * -log2e
            const float gn = nl + nh;     // * 2log2e

            const float r   = fsig_pre(gr);
            const float z   = fsig_pre(gz);
            const float omz = 1.0f - z;       // off n-path
            const float zh2 = z * h;          // off n-path
            const float n   = ftanh_pre(fmaf(r, gn, cn));
            h = fmaf(omz, n, zh2);

            BCAST(h, hp);

            // overrun guard: amortized 1/GUARD steps (uniform branch)
            if ((t & (GUARD - 1)) == 0) {
                while (t - ld_acquire_s32(cons_a) > (RING - GUARD)) { }
            }
            // lane 0 has the full row after BCAST; single-thread program order
            // makes the release-store publish all four row stores.
            if (lane == 0) {
                uint32_t sa = ring_a + (uint32_t)((t & (RING - 1)) * 64);
                sts_v2u64(sa,      hp[0], hp[1]);
                sts_v2u64(sa + 16, hp[2], hp[3]);
                sts_v2u64(sa + 32, hp[4], hp[5]);
                sts_v2u64(sa + 48, hp[6], hp[7]);
                st_release_s32(prod_a, t + 1);
            }
        }
    } else {
        // ================= consumer: output projection =================
        const int o0 = lane * 4;
        ull wv[4][8];
        ull bo2[4];
#pragma unroll
        for (int oo = 0; oo < 4; oo++) {
            bo2[oo] = pk(b_out[o0 + oo], 0.0f);
#pragma unroll
            for (int i = 0; i < 8; i++) {
                const int k0 = 2 * i, k1 = 2 * i + 1;
                float w0 = W_out[(o0 + oo) * HH + k0];
                float w1 = (k1 < HH) ? W_out[(o0 + oo) * HH + k1] : 0.0f;
                wv[oo][i] = pk(w0, w1);
            }
        }

        float* op = out + (size_t)b * OO + o0;

        for (int t = 0; t < TT; t++) {
            while (ld_acquire_s32(prod_a) <= t) { }

            uint32_t sa = ring_a + (uint32_t)((t & (RING - 1)) * 64);
            ull hp[8];
            lds_v2u64(sa,      hp[0], hp[1]);
            lds_v2u64(sa + 16, hp[2], hp[3]);
            lds_v2u64(sa + 32, hp[4], hp[5]);
            lds_v2u64(sa + 48, hp[6], hp[7]);

            ull acc0 = bo2[0], acc1 = bo2[1], acc2 = bo2[2], acc3 = bo2[3];
#pragma unroll
            for (int i = 0; i < 8; i++) {       // 4 independent chains, no dep stalls
                acc0 = fma2(wv[0][i], hp[i], acc0);
                acc1 = fma2(wv[1][i], hp[i], acc1);
                acc2 = fma2(wv[2][i], hp[i], acc2);
                acc3 = fma2(wv[3][i], hp[i], acc3);
            }
            float l0, h0v, l1, h1v, l2, h2v, l3, h3v;
            upk(acc0, l0, h0v); upk(acc1, l1, h1v);
            upk(acc2, l2, h2v); upk(acc3, l3, h3v);
            float4 v = make_float4(fsig(l0 + h0v), fsig(l1 + h1v),
                                   fsig(l2 + h2v), fsig(l3 + h3v));
            *reinterpret_cast<float4*>(op) = v;
            op += (size_t)BB * OO;

            if (lane == 0) st_release_s32(cons_a, t + 1);
        }
    }
}

extern "C" void kernel_launch(void* const* d_in, const int* in_sizes, int n_in,
                              void* d_out, int out_size)
{
    (void)in_sizes; (void)n_in; (void)out_size;
    const float* feed  = (const float*)d_in[0];
    const float* h0    = (const float*)d_in[1];
    const float* W_ih  = (const float*)d_in[2];
    const float* W_hh  = (const float*)d_in[3];
    const float* b_ih  = (const float*)d_in[4];
    const float* b_hh  = (const float*)d_in[5];
    const float* W_out = (const float*)d_in[6];
    const float* b_out = (const float*)d_in[7];
    float* out = (float*)d_out;

    gru_fused<<<128, 256>>>(feed, h0, W_ih, W_hh, b_ih, b_hh, W_out, b_out, out);
}

// round 8
// speedup vs baseline: 1.5507x; 1.1646x over previous
#include <cuda_runtime.h>
#include <cstdint>

#define TT 1024
#define BB 512
#define HH 15
#define II 10
#define OO 128
#define RING 32          // h-row ring depth per batch (power of 2)
#define GUARD 16         // producer checks consumer every GUARD steps

typedef unsigned long long ull;

__device__ __forceinline__ ull pk(float lo, float hi) {
    ull r; asm("mov.b64 %0, {%1, %2};" : "=l"(r) : "f"(lo), "f"(hi)); return r;
}
__device__ __forceinline__ void upk(ull v, float& lo, float& hi) {
    asm("mov.b64 {%0, %1}, %2;" : "=f"(lo), "=f"(hi) : "l"(v));
}
__device__ __forceinline__ ull fma2(ull a, ull b, ull c) {
    ull d; asm("fma.rn.f32x2 %0, %1, %2, %3;" : "=l"(d) : "l"(a), "l"(b), "l"(c)); return d;
}
__device__ __forceinline__ ull add2(ull a, ull b) {
    ull d; asm("add.rn.f32x2 %0, %1, %2;" : "=l"(d) : "l"(a), "l"(b)); return d;
}

// Pre-scaled sigmoid: input g already multiplied by -log2(e):  1/(1+2^g)
__device__ __forceinline__ float fsig_pre(float g) {
    float e; asm("ex2.approx.f32 %0, %1;" : "=f"(e) : "f"(g));
    float d = e + 1.0f;
    float r; asm("rcp.approx.f32 %0, %1;" : "=f"(r) : "f"(d));
    return r;
}
// Pre-scaled tanh: input g already multiplied by 2*log2(e): 1 - 2/(1+2^g)
__device__ __forceinline__ float ftanh_pre(float g) {
    float e; asm("ex2.approx.f32 %0, %1;" : "=f"(e) : "f"(g));
    float d = e + 1.0f;
    float r; asm("rcp.approx.f32 %0, %1;" : "=f"(r) : "f"(d));
    return fmaf(-2.0f, r, 1.0f);
}
// Plain accurate sigmoid (projection)
__device__ __forceinline__ float fsig(float x) {
    float e; asm("ex2.approx.f32 %0, %1;" : "=f"(e) : "f"(-1.4426950408889634f * x));
    float d = e + 1.0f;
    float r; asm("rcp.approx.f32 %0, %1;" : "=f"(r) : "f"(d));
    return r;
}

#define NEG_LOG2E (-1.4426950408889634f)
#define TWO_LOG2E ( 2.8853900817779268f)

__device__ __forceinline__ uint32_t smem_u32(const void* p) {
    uint32_t a;
    asm("{ .reg .u64 t; cvta.to.shared.u64 t, %1; cvt.u32.u64 %0, t; }" : "=r"(a) : "l"(p));
    return a;
}
__device__ __forceinline__ void sts_f32(uint32_t addr, float v) {
    asm volatile("st.shared.f32 [%0], %1;" :: "r"(addr), "f"(v) : "memory");
}
__device__ __forceinline__ void lds_v2u64(uint32_t addr, ull& a, ull& b) {
    asm volatile("ld.shared.v2.u64 {%0, %1}, [%2];" : "=l"(a), "=l"(b) : "r"(addr) : "memory");
}
__device__ __forceinline__ void st_release_s32(uint32_t addr, int v) {
    asm volatile("st.release.cta.shared.u32 [%0], %1;" :: "r"(addr), "r"(v) : "memory");
}
__device__ __forceinline__ int ld_acquire_s32(uint32_t addr) {
    int v; asm volatile("ld.acquire.cta.shared.u32 %0, [%1];" : "=r"(v) : "r"(addr) : "memory");
    return v;
}

// ---------------------------------------------------------------------------
// Fused persistent kernel. Block = 8 warps:
//   warps 4..7 : GRU recurrence producers (HIGH wid -> arbiter priority)
//   warps 0..3 : output projection consumers
// Hidden rows flow through a 32-deep smem ring with release/acquire counters.
// Producer publishes h scalars to the ring (1 predicated STS), then reloads
// the row itself as packed f32x2 pairs — the ring doubles as the h broadcast,
// replacing the 15-SHFL rebroadcast entirely. Spin loops nanosleep-throttled
// to keep the MIO/LSU pipe clear for the producer's critical-path STS/LDS.
// ---------------------------------------------------------------------------
__global__ void __launch_bounds__(256, 1) gru_fused(
    const float* __restrict__ feed, const float* __restrict__ h0,
    const float* __restrict__ W_ih, const float* __restrict__ W_hh,
    const float* __restrict__ b_ih, const float* __restrict__ b_hh,
    const float* __restrict__ W_out, const float* __restrict__ b_out,
    float* __restrict__ out)
{
    __shared__ __align__(16) float hring[4][RING][16];   // 8 KB
    __shared__ int prod[4];
    __shared__ int cons[4];

    const int tid  = threadIdx.x;
    const int wid  = tid >> 5;
    const int lane = tid & 31;
    const int bl   = wid & 3;                       // batch slot within block
    const int b    = blockIdx.x * 4 + bl;           // global batch (128 blocks x 4)

    // zero ring (slot column 15 must stay 0 forever) + counters
    for (int i = tid; i < 4 * RING * 16; i += 256)
        (&hring[0][0][0])[i] = 0.0f;
    if (tid < 4) { prod[tid] = 0; cons[tid] = 0; }
    __syncthreads();

    const uint32_t ring_a = smem_u32(&hring[bl][0][0]);
    const uint32_t prod_a = smem_u32(&prod[bl]);
    const uint32_t cons_a = smem_u32(&cons[bl]);

    if (wid >= 4) {
        // ================= producer: recurrence =================
        const int j = (lane < HH) ? lane : 0;       // inactive lanes shadow unit 0

        // W_hh rows j (r), 15+j (z), 30+j (n) packed over k, pre-scaled per gate
        ull wr[8], wz[8], wn[8];
#pragma unroll
        for (int i = 0; i < 8; i++) {
            const int k0 = 2 * i, k1 = 2 * i + 1;
            float r0 = W_hh[j * HH + k0]            * NEG_LOG2E;
            float z0 = W_hh[(HH + j) * HH + k0]     * NEG_LOG2E;
            float n0 = W_hh[(2 * HH + j) * HH + k0] * TWO_LOG2E;
            float r1 = (k1 < HH) ? W_hh[j * HH + k1]            * NEG_LOG2E : 0.0f;
            float z1 = (k1 < HH) ? W_hh[(HH + j) * HH + k1]     * NEG_LOG2E : 0.0f;
            float n1 = (k1 < HH) ? W_hh[(2 * HH + j) * HH + k1] * TWO_LOG2E : 0.0f;
            wr[i] = pk(r0, r1); wz[i] = pk(z0, z1); wn[i] = pk(n0, n1);
        }

        float cr = b_ih[j]          + b_hh[j];
        float cz = b_ih[HH + j]     + b_hh[HH + j];
        float cn = b_ih[2 * HH + j];
        float bn = b_hh[2 * HH + j] * TWO_LOG2E;
#pragma unroll
        for (int k = 0; k < II; k++) {
            float xk = feed[b * II + k];
            cr = fmaf(xk, W_ih[j * II + k],            cr);
            cz = fmaf(xk, W_ih[(HH + j) * II + k],     cz);
            cn = fmaf(xk, W_ih[(2 * HH + j) * II + k], cn);
        }
        cr *= NEG_LOG2E;
        cz *= NEG_LOG2E;
        cn *= TWO_LOG2E;

        float h = (lane < HH) ? h0[b * HH + j] : 0.0f;

        const ull crp = pk(cr, 0.0f);
        const ull czp = pk(cz, 0.0f);
        const ull bnp = pk(bn, 0.0f);

        // prime: publish initial h into scratch slot (RING-1) and reload packed.
        // Safe: consumer cannot touch slot RING-1 until prod >= RING, and the
        // producer rewrites it with real data at t = RING-1.
        {
            uint32_t sa = ring_a + (uint32_t)((RING - 1) * 64);
            if (lane < HH) sts_f32(sa + (uint32_t)lane * 4, h);
            __syncwarp();
        }

        ull hp[8];
        {
            uint32_t sa = ring_a + (uint32_t)((RING - 1) * 64);
            lds_v2u64(sa,      hp[0], hp[1]);
            lds_v2u64(sa + 16, hp[2], hp[3]);
            lds_v2u64(sa + 32, hp[4], hp[5]);
            lds_v2u64(sa + 48, hp[6], hp[7]);
        }

#pragma unroll 2
        for (int t = 0; t < TT; t++) {
            // gate dots: 6 independent f32x2 chains
            ull ar0 = crp, az0 = czp, an0 = bnp;
            ull ar1 = 0ULL, az1 = 0ULL, an1 = 0ULL;
#pragma unroll
            for (int i = 0; i < 4; i++) {
                ar0 = fma2(wr[i], hp[i], ar0);
                az0 = fma2(wz[i], hp[i], az0);
                an0 = fma2(wn[i], hp[i], an0);
            }
#pragma unroll
            for (int i = 4; i < 8; i++) {
                ar1 = fma2(wr[i], hp[i], ar1);
                az1 = fma2(wz[i], hp[i], az1);
                an1 = fma2(wn[i], hp[i], an1);
            }
            float rl, rh, zl, zh, nl, nh;
            upk(add2(ar0, ar1), rl, rh);
            upk(add2(az0, az1), zl, zh);
            upk(add2(an0, an1), nl, nh);
            const float gr = rl + rh;     // * -log2e
            const float gz = zl + zh;     // * -log2e
            const float gn = nl + nh;     // * 2log2e

            const float r   = fsig_pre(gr);
            const float z   = fsig_pre(gz);
            const float omz = 1.0f - z;       // off n-path
            const float zh2 = z * h;          // off n-path
            const float n   = ftanh_pre(fmaf(r, gn, cn));
            h = fmaf(omz, n, zh2);

            // overrun guard: amortized 1/GUARD steps (uniform branch)
            if ((t & (GUARD - 1)) == 0) {
                while (t - ld_acquire_s32(cons_a) > (RING - GUARD)) { __nanosleep(32); }
            }

            // publish h scalars -> ring slot (1 predicated STS), order with
            // syncwarp, release counter, then reload packed for next step.
            const uint32_t sa = ring_a + (uint32_t)((t & (RING - 1)) * 64);
            if (lane < HH) sts_f32(sa + (uint32_t)lane * 4, h);
            __syncwarp();
            if (lane == 0) st_release_s32(prod_a, t + 1);

            lds_v2u64(sa,      hp[0], hp[1]);
            lds_v2u64(sa + 16, hp[2], hp[3]);
            lds_v2u64(sa + 32, hp[4], hp[5]);
            lds_v2u64(sa + 48, hp[6], hp[7]);
        }
    } else {
        // ================= consumer: output projection =================
        const int o0 = lane * 4;
        ull wv[4][8];
        ull bo2[4];
#pragma unroll
        for (int oo = 0; oo < 4; oo++) {
            bo2[oo] = pk(b_out[o0 + oo], 0.0f);
#pragma unroll
            for (int i = 0; i < 8; i++) {
                const int k0 = 2 * i, k1 = 2 * i + 1;
                float w0 = W_out[(o0 + oo) * HH + k0];
                float w1 = (k1 < HH) ? W_out[(o0 + oo) * HH + k1] : 0.0f;
                wv[oo][i] = pk(w0, w1);
            }
        }

        float* op = out + (size_t)b * OO + o0;

        for (int t = 0; t < TT; t++) {
            // throttled spin: keep the LSU/MIO pipe clear for producers
            while (ld_acquire_s32(prod_a) <= t) { __nanosleep(32); }

            uint32_t sa = ring_a + (uint32_t)((t & (RING - 1)) * 64);
            ull hp[8];
            lds_v2u64(sa,      hp[0], hp[1]);
            lds_v2u64(sa + 16, hp[2], hp[3]);
            lds_v2u64(sa + 32, hp[4], hp[5]);
            lds_v2u64(sa + 48, hp[6], hp[7]);

            ull acc0 = bo2[0], acc1 = bo2[1], acc2 = bo2[2], acc3 = bo2[3];
#pragma unroll
            for (int i = 0; i < 8; i++) {       // 4 independent chains
                acc0 = fma2(wv[0][i], hp[i], acc0);
                acc1 = fma2(wv[1][i], hp[i], acc1);
                acc2 = fma2(wv[2][i], hp[i], acc2);
                acc3 = fma2(wv[3][i], hp[i], acc3);
            }
            float l0, h0v, l1, h1v, l2, h2v, l3, h3v;
            upk(acc0, l0, h0v); upk(acc1, l1, h1v);
            upk(acc2, l2, h2v); upk(acc3, l3, h3v);
            float4 v = make_float4(fsig(l0 + h0v), fsig(l1 + h1v),
                                   fsig(l2 + h2v), fsig(l3 + h3v));
            *reinterpret_cast<float4*>(op) = v;
            op += (size_t)BB * OO;

            if (lane == 0) st_release_s32(cons_a, t + 1);
        }
    }
}

extern "C" void kernel_launch(void* const* d_in, const int* in_sizes, int n_in,
                              void* d_out, int out_size)
{
    (void)in_sizes; (void)n_in; (void)out_size;
    const float* feed  = (const float*)d_in[0];
    const float* h0    = (const float*)d_in[1];
    const float* W_ih  = (const float*)d_in[2];
    const float* W_hh  = (const float*)d_in[3];
    const float* b_ih  = (const float*)d_in[4];
    const float* b_hh  = (const float*)d_in[5];
    const float* W_out = (const float*)d_in[6];
    const float* b_out = (const float*)d_in[7];
    float* out = (float*)d_out;

    gru_fused<<<128, 256>>>(feed, h0, W_ih, W_hh, b_ih, b_hh, W_out, b_out, out);
}

// round 9
// speedup vs baseline: 1.5580x; 1.0047x over previous
#include <cuda_runtime.h>
#include <cstdint>

#define TT 1024
#define BB 512
#define HH 15
#define II 10
#define OO 128
#define RING 32          // h-row ring depth per batch (power of 2)
#define PUB 8            // producer publishes every PUB steps
#define GUARD 16         // producer checks consumer every GUARD steps

typedef unsigned long long ull;

__device__ __forceinline__ ull pk(float lo, float hi) {
    ull r; asm("mov.b64 %0, {%1, %2};" : "=l"(r) : "f"(lo), "f"(hi)); return r;
}
__device__ __forceinline__ void upk(ull v, float& lo, float& hi) {
    asm("mov.b64 {%0, %1}, %2;" : "=f"(lo), "=f"(hi) : "l"(v));
}
__device__ __forceinline__ ull fma2(ull a, ull b, ull c) {
    ull d; asm("fma.rn.f32x2 %0, %1, %2, %3;" : "=l"(d) : "l"(a), "l"(b), "l"(c)); return d;
}
__device__ __forceinline__ ull add2(ull a, ull b) {
    ull d; asm("add.rn.f32x2 %0, %1, %2;" : "=l"(d) : "l"(a), "l"(b)); return d;
}
__device__ __forceinline__ float ftanh_mufu(float x) {
    float r; asm("tanh.approx.f32 %0, %1;" : "=f"(r) : "f"(x)); return r;
}
// Accurate sigmoid (output layer only; off the critical path)
__device__ __forceinline__ float fsig(float x) {
    float e; asm("ex2.approx.f32 %0, %1;" : "=f"(e) : "f"(-1.4426950408889634f * x));
    float d = e + 1.0f;
    float r; asm("rcp.approx.f32 %0, %1;" : "=f"(r) : "f"(d));
    return r;
}

__device__ __forceinline__ uint32_t smem_u32(const void* p) {
    uint32_t a;
    asm("{ .reg .u64 t; cvta.to.shared.u64 t, %1; cvt.u32.u64 %0, t; }" : "=r"(a) : "l"(p));
    return a;
}
__device__ __forceinline__ void sts_f32(uint32_t addr, float v) {
    asm volatile("st.shared.f32 [%0], %1;" :: "r"(addr), "f"(v) : "memory");
}
__device__ __forceinline__ void lds_v2u64(uint32_t addr, ull& a, ull& b) {
    asm volatile("ld.shared.v2.u64 {%0, %1}, [%2];" : "=l"(a), "=l"(b) : "r"(addr) : "memory");
}
__device__ __forceinline__ void st_release_s32(uint32_t addr, int v) {
    asm volatile("st.release.cta.shared.u32 [%0], %1;" :: "r"(addr), "r"(v) : "memory");
}
__device__ __forceinline__ int ld_acquire_s32(uint32_t addr) {
    int v; asm volatile("ld.acquire.cta.shared.u32 %0, [%1];" : "=r"(v) : "r"(addr) : "memory");
    return v;
}

// ---------------------------------------------------------------------------
// Fused persistent kernel. Block = 8 warps:
//   warps 4..7 : GRU recurrence producers (HIGH wid -> arbiter priority)
//   warps 0..3 : output projection consumers
// Ring publish amortized to every PUB steps; inner loop branch-free.
// Recurrence activations via single-MUFU tanh.approx:
//   sigmoid(x) = 0.5*tanh(x/2)+0.5  (r/z weights pre-scaled by 0.5)
//   tanh(x)    = tanh.approx(x)     (n weights unscaled)
// ---------------------------------------------------------------------------
__global__ void __launch_bounds__(256, 1) gru_fused(
    const float* __restrict__ feed, const float* __restrict__ h0,
    const float* __restrict__ W_ih, const float* __restrict__ W_hh,
    const float* __restrict__ b_ih, const float* __restrict__ b_hh,
    const float* __restrict__ W_out, const float* __restrict__ b_out,
    float* __restrict__ out)
{
    __shared__ __align__(16) float hring[4][RING][16];   // 8 KB
    __shared__ int prod[4];
    __shared__ int cons[4];

    const int tid  = threadIdx.x;
    const int wid  = tid >> 5;
    const int lane = tid & 31;
    const int bl   = wid & 3;                       // batch slot within block
    const int b    = blockIdx.x * 4 + bl;           // global batch (128 blocks x 4)

    // zero ring (column 15 of every slot must stay 0 forever) + counters
    for (int i = tid; i < 4 * RING * 16; i += 256)
        (&hring[0][0][0])[i] = 0.0f;
    if (tid < 4) { prod[tid] = 0; cons[tid] = 0; }
    __syncthreads();

    const uint32_t ring_a = smem_u32(&hring[bl][0][0]);
    const uint32_t prod_a = smem_u32(&prod[bl]);
    const uint32_t cons_a = smem_u32(&cons[bl]);

    if (wid >= 4) {
        // ================= producer: recurrence =================
        const int j = (lane < HH) ? lane : 0;       // inactive lanes shadow unit 0

        // W_hh rows j (r), 15+j (z) scaled by 0.5 ; 30+j (n) unscaled
        ull wr[8], wz[8], wn[8];
#pragma unroll
        for (int i = 0; i < 8; i++) {
            const int k0 = 2 * i, k1 = 2 * i + 1;
            float r0 = W_hh[j * HH + k0]            * 0.5f;
            float z0 = W_hh[(HH + j) * HH + k0]     * 0.5f;
            float n0 = W_hh[(2 * HH + j) * HH + k0];
            float r1 = (k1 < HH) ? W_hh[j * HH + k1]            * 0.5f : 0.0f;
            float z1 = (k1 < HH) ? W_hh[(HH + j) * HH + k1]     * 0.5f : 0.0f;
            float n1 = (k1 < HH) ? W_hh[(2 * HH + j) * HH + k1]        : 0.0f;
            wr[i] = pk(r0, r1); wz[i] = pk(z0, z1); wn[i] = pk(n0, n1);
        }

        // gate constants: cr/cz folded with both biases (scaled 0.5);
        // cn = i_n (unscaled) ; bn = b_hh_n (unscaled, inside the r* term)
        float cr = b_ih[j]          + b_hh[j];
        float cz = b_ih[HH + j]     + b_hh[HH + j];
        float cn = b_ih[2 * HH + j];
        float bn = b_hh[2 * HH + j];
#pragma unroll
        for (int k = 0; k < II; k++) {
            float xk = feed[b * II + k];
            cr = fmaf(xk, W_ih[j * II + k],            cr);
            cz = fmaf(xk, W_ih[(HH + j) * II + k],     cz);
            cn = fmaf(xk, W_ih[(2 * HH + j) * II + k], cn);
        }
        cr *= 0.5f;
        cz *= 0.5f;

        float h = (lane < HH) ? h0[b * HH + j] : 0.0f;

        const ull crp = pk(cr, 0.0f);
        const ull czp = pk(cz, 0.0f);
        const ull bnp = pk(bn, 0.0f);

        // prime: publish initial h into scratch slot RING-1, reload packed.
        {
            uint32_t sa = ring_a + (uint32_t)((RING - 1) * 64);
            if (lane < HH) sts_f32(sa + (uint32_t)lane * 4, h);
            __syncwarp();
        }
        ull hp[8];
        {
            uint32_t sa = ring_a + (uint32_t)((RING - 1) * 64);
            lds_v2u64(sa,      hp[0], hp[1]);
            lds_v2u64(sa + 16, hp[2], hp[3]);
            lds_v2u64(sa + 32, hp[4], hp[5]);
            lds_v2u64(sa + 48, hp[6], hp[7]);
        }

        for (int t0 = 0; t0 < TT; t0 += PUB) {
            // overrun guard at chunk boundary (every GUARD steps)
            if ((t0 & (GUARD - 1)) == 0) {
                while (t0 - ld_acquire_s32(cons_a) > (RING - GUARD)) { __nanosleep(32); }
            }
#pragma unroll
            for (int tt = 0; tt < PUB; tt++) {
                const int t = t0 + tt;
                // gate dots: 6 independent f32x2 chains
                ull ar0 = crp, az0 = czp, an0 = bnp;
                ull ar1 = 0ULL, az1 = 0ULL, an1 = 0ULL;
#pragma unroll
                for (int i = 0; i < 4; i++) {
                    ar0 = fma2(wr[i], hp[i], ar0);
                    az0 = fma2(wz[i], hp[i], az0);
                    an0 = fma2(wn[i], hp[i], an0);
                }
#pragma unroll
                for (int i = 4; i < 8; i++) {
                    ar1 = fma2(wr[i], hp[i], ar1);
                    az1 = fma2(wz[i], hp[i], az1);
                    an1 = fma2(wn[i], hp[i], an1);
                }
                float rl, rh, zl, zh, nl, nh;
                upk(add2(ar0, ar1), rl, rh);
                upk(add2(az0, az1), zl, zh);
                upk(add2(an0, an1), nl, nh);
                const float gr = rl + rh;     // (r-gate preact) * 0.5
                const float gz = zl + zh;     // (z-gate preact) * 0.5
                const float gn = nl + nh;     // h-dot + b_hh_n, unscaled

                const float tr  = ftanh_mufu(gr);
                const float tz  = ftanh_mufu(gz);
                const float r   = fmaf(0.5f, tr, 0.5f);       // sigmoid
                const float omz = fmaf(-0.5f, tz, 0.5f);      // 1 - z
                const float z   = fmaf(0.5f, tz, 0.5f);
                const float zh2 = z * h;                      // off n-path
                const float n   = ftanh_mufu(fmaf(r, gn, cn));
                h = fmaf(omz, n, zh2);

                // publish h scalars -> ring slot; reload packed for next step
                const uint32_t sa = ring_a + (uint32_t)((t & (RING - 1)) * 64);
                if (lane < HH) sts_f32(sa + (uint32_t)lane * 4, h);
                __syncwarp();
                lds_v2u64(sa,      hp[0], hp[1]);
                lds_v2u64(sa + 16, hp[2], hp[3]);
                lds_v2u64(sa + 32, hp[4], hp[5]);
                lds_v2u64(sa + 48, hp[6], hp[7]);
            }
            // amortized release: publish the whole chunk at once
            if (lane == 0) st_release_s32(prod_a, t0 + PUB);
        }
    } else {
        // ================= consumer: output projection =================
        const int o0 = lane * 4;
        ull wv[4][8];
        ull bo2[4];
#pragma unroll
        for (int oo = 0; oo < 4; oo++) {
            bo2[oo] = pk(b_out[o0 + oo], 0.0f);
#pragma unroll
            for (int i = 0; i < 8; i++) {
                const int k0 = 2 * i, k1 = 2 * i + 1;
                float w0 = W_out[(o0 + oo) * HH + k0];
                float w1 = (k1 < HH) ? W_out[(o0 + oo) * HH + k1] : 0.0f;
                wv[oo][i] = pk(w0, w1);
            }
        }

        float* op = out + (size_t)b * OO + o0;

        for (int t = 0; t < TT; t++) {
            // throttled spin; producer publishes in chunks of PUB
            while (ld_acquire_s32(prod_a) <= t) { __nanosleep(32); }

            uint32_t sa = ring_a + (uint32_t)((t & (RING - 1)) * 64);
            ull hp[8];
            lds_v2u64(sa,      hp[0], hp[1]);
            lds_v2u64(sa + 16, hp[2], hp[3]);
            lds_v2u64(sa + 32, hp[4], hp[5]);
            lds_v2u64(sa + 48, hp[6], hp[7]);

            ull acc0 = bo2[0], acc1 = bo2[1], acc2 = bo2[2], acc3 = bo2[3];
#pragma unroll
            for (int i = 0; i < 8; i++) {       // 4 independent chains
                acc0 = fma2(wv[0][i], hp[i], acc0);
                acc1 = fma2(wv[1][i], hp[i], acc1);
                acc2 = fma2(wv[2][i], hp[i], acc2);
                acc3 = fma2(wv[3][i], hp[i], acc3);
            }
            float l0, h0v, l1, h1v, l2, h2v, l3, h3v;
            upk(acc0, l0, h0v); upk(acc1, l1, h1v);
            upk(acc2, l2, h2v); upk(acc3, l3, h3v);
            float4 v = make_float4(fsig(l0 + h0v), fsig(l1 + h1v),
                                   fsig(l2 + h2v), fsig(l3 + h3v));
            *reinterpret_cast<float4*>(op) = v;
            op += (size_t)BB * OO;

            if ((t & (PUB - 1)) == (PUB - 1) && lane == 0)
                st_release_s32(cons_a, t + 1);
        }
    }
}

extern "C" void kernel_launch(void* const* d_in, const int* in_sizes, int n_in,
                              void* d_out, int out_size)
{
    (void)in_sizes; (void)n_in; (void)out_size;
    const float* feed  = (const float*)d_in[0];
    const float* h0    = (const float*)d_in[1];
    const float* W_ih  = (const float*)d_in[2];
    const float* W_hh  = (const float*)d_in[3];
    const float* b_ih  = (const float*)d_in[4];
    const float* b_hh  = (const float*)d_in[5];
    const float* W_out = (const float*)d_in[6];
    const float* b_out = (const float*)d_in[7];
    float* out = (float*)d_out;

    gru_fused<<<128, 256>>>(feed, h0, W_ih, W_hh, b_ih, b_hh, W_out, b_out, out);
}

// round 13
// speedup vs baseline: 2.3784x; 1.5265x over previous
#include <cuda_runtime.h>
#include <cstdint>

#define TT 1024
#define BB 512
#define HH 15
#define II 10
#define OO 128
#define RING 32          // h-row ring depth per batch (power of 2)
#define PUB 8            // producer publishes every PUB steps
#define GUARD 16         // producer checks consumers every GUARD steps

typedef unsigned long long ull;

__device__ __forceinline__ ull pk(float lo, float hi) {
    ull r; asm("mov.b64 %0, {%1, %2};" : "=l"(r) : "f"(lo), "f"(hi)); return r;
}
__device__ __forceinline__ void upk(ull v, float& lo, float& hi) {
    asm("mov.b64 {%0, %1}, %2;" : "=f"(lo), "=f"(hi) : "l"(v));
}
__device__ __forceinline__ ull fma2(ull a, ull b, ull c) {
    ull d; asm("fma.rn.f32x2 %0, %1, %2, %3;" : "=l"(d) : "l"(a), "l"(b), "l"(c)); return d;
}
__device__ __forceinline__ ull add2(ull a, ull b) {
    ull d; asm("add.rn.f32x2 %0, %1, %2;" : "=l"(d) : "l"(a), "l"(b)); return d;
}
__device__ __forceinline__ float ftanh_mufu(float x) {
    float r; asm("tanh.approx.f32 %0, %1;" : "=f"(r) : "f"(x)); return r;
}
// Accurate sigmoid (output layer; not on the recurrence critical path)
__device__ __forceinline__ float fsig(float x) {
    float e; asm("ex2.approx.f32 %0, %1;" : "=f"(e) : "f"(-1.4426950408889634f * x));
    float d = e + 1.0f;
    float r; asm("rcp.approx.f32 %0, %1;" : "=f"(r) : "f"(d));
    return r;
}

__device__ __forceinline__ uint32_t smem_u32(const void* p) {
    uint32_t a;
    asm("{ .reg .u64 t; cvta.to.shared.u64 t, %1; cvt.u32.u64 %0, t; }" : "=r"(a) : "l"(p));
    return a;
}
__device__ __forceinline__ void sts_f32(uint32_t addr, float v) {
    asm volatile("st.shared.f32 [%0], %1;" :: "r"(addr), "f"(v) : "memory");
}
__device__ __forceinline__ void lds_v2u64(uint32_t addr, ull& a, ull& b) {
    asm volatile("ld.shared.v2.u64 {%0, %1}, [%2];" : "=l"(a), "=l"(b) : "r"(addr) : "memory");
}
__device__ __forceinline__ void st_release_s32(uint32_t addr, int v) {
    asm volatile("st.release.cta.shared.u32 [%0], %1;" :: "r"(addr), "r"(v) : "memory");
}
__device__ __forceinline__ int ld_acquire_s32(uint32_t addr) {
    int v; asm volatile("ld.acquire.cta.shared.u32 %0, [%1];" : "=r"(v) : "r"(addr) : "memory");
    return v;
}

// ---------------------------------------------------------------------------
// Fused persistent kernel. Block = 12 warps (384 threads):
//   warps 8..11 : GRU recurrence producers (HIGHEST wid -> arbiter priority,
//                 one per SMSP)
//   warps 0..7  : output projection consumers, TWO per batch, parity-split
//                 over t (half=0 even t, half=1 odd t)
// Hidden rows flow through a 32-deep smem ring; consumers pace the producer
// through min of two cons counters.
// ---------------------------------------------------------------------------
__global__ void __launch_bounds__(384, 1) gru_fused(
    const float* __restrict__ feed, const float* __restrict__ h0,
    const float* __restrict__ W_ih, const float* __restrict__ W_hh,
    const float* __restrict__ b_ih, const float* __restrict__ b_hh,
    const float* __restrict__ W_out, const float* __restrict__ b_out,
    float* __restrict__ out)
{
    __shared__ __align__(16) float hring[4][RING][16];   // 8 KB
    __shared__ int prod[4];
    __shared__ int cons[4][2];

    const int tid  = threadIdx.x;
    const int wid  = tid >> 5;
    const int lane = tid & 31;

    // zero ring (column 15 of every slot must stay 0 forever) + counters
    for (int i = tid; i < 4 * RING * 16; i += 384)
        (&hring[0][0][0])[i] = 0.0f;
    if (tid < 4) prod[tid] = 0;
    if (tid < 8) cons[tid >> 1][tid & 1] = 0;
    __syncthreads();

    if (wid >= 8) {
        // ================= producer: recurrence =================
        const int bl = wid - 8;
        const int b  = blockIdx.x * 4 + bl;
        const uint32_t ring_a  = smem_u32(&hring[bl][0][0]);
        const uint32_t prod_a  = smem_u32(&prod[bl]);
        const uint32_t cons_a0 = smem_u32(&cons[bl][0]);
        const uint32_t cons_a1 = smem_u32(&cons[bl][1]);

        const int j = (lane < HH) ? lane : 0;       // inactive lanes shadow unit 0

        // W_hh rows j (r), 15+j (z) scaled by 0.5 ; 30+j (n) unscaled
        ull wr[8], wz[8], wn[8];
#pragma unroll
        for (int i = 0; i < 8; i++) {
            const int k0 = 2 * i, k1 = 2 * i + 1;
            float r0 = W_hh[j * HH + k0]            * 0.5f;
            float z0 = W_hh[(HH + j) * HH + k0]     * 0.5f;
            float n0 = W_hh[(2 * HH + j) * HH + k0];
            float r1 = (k1 < HH) ? W_hh[j * HH + k1]            * 0.5f : 0.0f;
            float z1 = (k1 < HH) ? W_hh[(HH + j) * HH + k1]     * 0.5f : 0.0f;
            float n1 = (k1 < HH) ? W_hh[(2 * HH + j) * HH + k1]        : 0.0f;
            wr[i] = pk(r0, r1); wz[i] = pk(z0, z1); wn[i] = pk(n0, n1);
        }

        float cr = b_ih[j]          + b_hh[j];
        float cz = b_ih[HH + j]     + b_hh[HH + j];
        float cn = b_ih[2 * HH + j];
        float bn = b_hh[2 * HH + j];
#pragma unroll
        for (int k = 0; k < II; k++) {
            float xk = feed[b * II + k];
            cr = fmaf(xk, W_ih[j * II + k],            cr);
            cz = fmaf(xk, W_ih[(HH + j) * II + k],     cz);
            cn = fmaf(xk, W_ih[(2 * HH + j) * II + k], cn);
        }
        cr *= 0.5f;
        cz *= 0.5f;

        float h = (lane < HH) ? h0[b * HH + j] : 0.0f;

        const ull crp = pk(cr, 0.0f);
        const ull czp = pk(cz, 0.0f);
        const ull bnp = pk(bn, 0.0f);

        // prime: publish initial h into scratch slot RING-1, reload packed.
        {
            uint32_t sa = ring_a + (uint32_t)((RING - 1) * 64);
            if (lane < HH) sts_f32(sa + (uint32_t)lane * 4, h);
            __syncwarp();
        }
        ull hp[8];
        {
            uint32_t sa = ring_a + (uint32_t)((RING - 1) * 64);
            lds_v2u64(sa,      hp[0], hp[1]);
            lds_v2u64(sa + 16, hp[2], hp[3]);
            lds_v2u64(sa + 32, hp[4], hp[5]);
            lds_v2u64(sa + 48, hp[6], hp[7]);
        }

        for (int t0 = 0; t0 < TT; t0 += PUB) {
            // overrun guard at chunk boundary (every GUARD steps):
            // need all t < t0-16 consumed by BOTH parity consumers
            if ((t0 & (GUARD - 1)) == 0) {
                for (;;) {
                    int c0 = ld_acquire_s32(cons_a0);
                    int c1 = ld_acquire_s32(cons_a1);
                    int cm = c0 < c1 ? c0 : c1;
                    if (t0 - cm <= (RING - GUARD)) break;
                    __nanosleep(32);
                }
            }
#pragma unroll
            for (int tt = 0; tt < PUB; tt++) {
                const int t = t0 + tt;
                // gate dots: 6 independent f32x2 chains
                ull ar0 = crp, az0 = czp, an0 = bnp;
                ull ar1 = 0ULL, az1 = 0ULL, an1 = 0ULL;
#pragma unroll
                for (int i = 0; i < 4; i++) {
                    ar0 = fma2(wr[i], hp[i], ar0);
                    az0 = fma2(wz[i], hp[i], az0);
                    an0 = fma2(wn[i], hp[i], an0);
                }
#pragma unroll
                for (int i = 4; i < 8; i++) {
                    ar1 = fma2(wr[i], hp[i], ar1);
                    az1 = fma2(wz[i], hp[i], az1);
                    an1 = fma2(wn[i], hp[i], an1);
                }
                float rl, rh, zl, zh, nl, nh;
                upk(add2(ar0, ar1), rl, rh);
                upk(add2(az0, az1), zl, zh);
                upk(add2(an0, an1), nl, nh);
                const float gr = rl + rh;     // (r preact) * 0.5
                const float gz = zl + zh;     // (z preact) * 0.5
                const float gn = nl + nh;     // h-dot + b_hh_n

                const float tr  = ftanh_mufu(gr);
                const float tz  = ftanh_mufu(gz);
                const float r   = fmaf(0.5f, tr, 0.5f);       // sigmoid
                const float omz = fmaf(-0.5f, tz, 0.5f);      // 1 - z
                const float z   = fmaf(0.5f, tz, 0.5f);
                const float zh2 = z * h;                      // off n-path
                const float n   = ftanh_mufu(fmaf(r, gn, cn));
                h = fmaf(omz, n, zh2);

                // publish h scalars -> ring slot; reload packed for next step
                const uint32_t sa = ring_a + (uint32_t)((t & (RING - 1)) * 64);
                if (lane < HH) sts_f32(sa + (uint32_t)lane * 4, h);
                __syncwarp();
                lds_v2u64(sa,      hp[0], hp[1]);
                lds_v2u64(sa + 16, hp[2], hp[3]);
                lds_v2u64(sa + 32, hp[4], hp[5]);
                lds_v2u64(sa + 48, hp[6], hp[7]);
            }
            // amortized release: publish the whole chunk at once
            if (lane == 0) st_release_s32(prod_a, t0 + PUB);
        }
    } else {
        // ================= consumer: output projection =================
        // two warps per batch, parity-split over t
        const int bl   = wid & 3;
        const int half = wid >> 2;                 // 0: even t, 1: odd t
        const int b    = blockIdx.x * 4 + bl;
        const uint32_t ring_a = smem_u32(&hring[bl][0][0]);
        const uint32_t prod_a = smem_u32(&prod[bl]);
        const uint32_t cons_a = smem_u32(&cons[bl][half]);

        const int o0 = lane * 4;
        ull wv[4][8];
        ull bo2[4];
#pragma unroll
        for (int oo = 0; oo < 4; oo++) {
            bo2[oo] = pk(b_out[o0 + oo], 0.0f);
#pragma unroll
            for (int i = 0; i < 8; i++) {
                const int k0 = 2 * i, k1 = 2 * i + 1;
                float w0 = W_out[(o0 + oo) * HH + k0];
                float w1 = (k1 < HH) ? W_out[(o0 + oo) * HH + k1] : 0.0f;
                wv[oo][i] = pk(w0, w1);
            }
        }

        float* op = out + (size_t)(half) * BB * OO + (size_t)b * OO + o0;

        for (int t = half; t < TT; t += 2) {
            // throttled spin; producer publishes in chunks of PUB
            while (ld_acquire_s32(prod_a) <= t) { __nanosleep(32); }

            uint32_t sa = ring_a + (uint32_t)((t & (RING - 1)) * 64);
            ull hp[8];
            lds_v2u64(sa,      hp[0], hp[1]);
            lds_v2u64(sa + 16, hp[2], hp[3]);
            lds_v2u64(sa + 32, hp[4], hp[5]);
            lds_v2u64(sa + 48, hp[6], hp[7]);

            ull acc0 = bo2[0], acc1 = bo2[1], acc2 = bo2[2], acc3 = bo2[3];
#pragma unroll
            for (int i = 0; i < 8; i++) {       // 4 independent chains
                acc0 = fma2(wv[0][i], hp[i], acc0);
                acc1 = fma2(wv[1][i], hp[i], acc1);
                acc2 = fma2(wv[2][i], hp[i], acc2);
                acc3 = fma2(wv[3][i], hp[i], acc3);
            }
            float l0, h0v, l1, h1v, l2, h2v, l3, h3v;
            upk(acc0, l0, h0v); upk(acc1, l1, h1v);
            upk(acc2, l2, h2v); upk(acc3, l3, h3v);
            float4 v = make_float4(fsig(l0 + h0v), fsig(l1 + h1v),
                                   fsig(l2 + h2v), fsig(l3 + h3v));
            *reinterpret_cast<float4*>(op) = v;
            op += (size_t)2 * BB * OO;

            // release every 8 own-iterations (16 t): counter = t rounded up to 16
            if ((t & 15) == (14 + half) && lane == 0)
                st_release_s32(cons_a, (t | 15) + 1);
        }
        // final release covers t=TT since TT%16==0; producer cannot hang on tail
    }
}

extern "C" void kernel_launch(void* const* d_in, const int* in_sizes, int n_in,
                              void* d_out, int out_size)
{
    (void)in_sizes; (void)n_in; (void)out_size;
    const float* feed  = (const float*)d_in[0];
    const float* h0    = (const float*)d_in[1];
    const float* W_ih  = (const float*)d_in[2];
    const float* W_hh  = (const float*)d_in[3];
    const float* b_ih  = (const float*)d_in[4];
    const float* b_hh  = (const float*)d_in[5];
    const float* W_out = (const float*)d_in[6];
    const float* b_out = (const float*)d_in[7];
    float* out = (float*)d_out;

    gru_fused<<<128, 384>>>(feed, h0, W_ih, W_hh, b_ih, b_hh, W_out, b_out, out);
}